// round 1
// baseline (speedup 1.0000x reference)
#include <cuda_runtime.h>

#define BB 64
#define TT 512
#define DD 512
#define UU 512
#define NG 2048   // 4*UU

// ---------------- device scratch (static: no allocations allowed) ----------------
__device__ float g_zx[(size_t)BB * TT * NG];      // 268 MB: x @ Wk for all timesteps
__device__ float g_zpart[(size_t)8 * BB * NG];    // 4 MB: split-K partials per step
__device__ float g_h[2][BB * UU];                 // double-buffered hidden state
__device__ float g_c[BB * UU];                    // cell state
__device__ unsigned g_bar_count;
__device__ unsigned g_bar_gen;

// ---------------- grid-wide barrier (all CTAs co-resident) ----------------
__device__ __forceinline__ void grid_barrier(int nblk) {
    __threadfence();            // make this thread's global writes visible at L2
    __syncthreads();
    if (threadIdx.x == 0) {
        unsigned gen = *(volatile unsigned*)&g_bar_gen;
        if (atomicAdd(&g_bar_count, 1) == (unsigned)(nblk - 1)) {
            g_bar_count = 0;
            __threadfence();
            atomicAdd(&g_bar_gen, 1);
        } else {
            while (*(volatile unsigned*)&g_bar_gen == gen) { __nanosleep(64); }
        }
    }
    __syncthreads();
}

// =======================================================================
// Phase 1: g_zx[M=32768, N=2048] = x[M, 512] @ Wk[512, 2048]
// 128x128 CTA tile, BK=8, 256 threads, 8x8 microtile (split 4+4 for
// conflict-free LDS.128).
// =======================================================================
__global__ __launch_bounds__(256) void sgemm_zx(const float* __restrict__ A,
                                                const float* __restrict__ Bm) {
    __shared__ float As[8][128];
    __shared__ float Bs[8][128];
    const int m0 = blockIdx.y * 128;
    const int n0 = blockIdx.x * 128;
    const int tid = threadIdx.x;
    const int trow = tid >> 4;          // 0..15
    const int tcol = tid & 15;          // 0..15
    const int aRow = tid >> 1, aCol = (tid & 1) * 4;
    const int bRow = tid >> 5, bCol = (tid & 31) * 4;

    float acc[8][8];
#pragma unroll
    for (int i = 0; i < 8; i++)
#pragma unroll
        for (int j = 0; j < 8; j++) acc[i][j] = 0.0f;

    const float* Aptr = A + (size_t)(m0 + aRow) * DD + aCol;
    const float* Bptr = Bm + (size_t)bRow * NG + n0 + bCol;

    for (int k0 = 0; k0 < DD; k0 += 8) {
        float4 av = __ldg((const float4*)(Aptr + k0));
        As[aCol + 0][aRow] = av.x;
        As[aCol + 1][aRow] = av.y;
        As[aCol + 2][aRow] = av.z;
        As[aCol + 3][aRow] = av.w;
        float4 bv = __ldg((const float4*)(Bptr + (size_t)k0 * NG));
        *(float4*)&Bs[bRow][bCol] = bv;
        __syncthreads();
#pragma unroll
        for (int k = 0; k < 8; k++) {
            float ar[8], br[8];
            *(float4*)&ar[0] = *(const float4*)&As[k][trow * 4];
            *(float4*)&ar[4] = *(const float4*)&As[k][64 + trow * 4];
            *(float4*)&br[0] = *(const float4*)&Bs[k][tcol * 4];
            *(float4*)&br[4] = *(const float4*)&Bs[k][64 + tcol * 4];
#pragma unroll
            for (int i = 0; i < 8; i++)
#pragma unroll
                for (int j = 0; j < 8; j++) acc[i][j] = fmaf(ar[i], br[j], acc[i][j]);
        }
        __syncthreads();
    }
#pragma unroll
    for (int i = 0; i < 8; i++) {
        int row = m0 + ((i < 4) ? (trow * 4 + i) : (64 + trow * 4 + i - 4));
        float* Cp = g_zx + (size_t)row * NG + n0;
        *(float4*)(Cp + tcol * 4)      = make_float4(acc[i][0], acc[i][1], acc[i][2], acc[i][3]);
        *(float4*)(Cp + 64 + tcol * 4) = make_float4(acc[i][4], acc[i][5], acc[i][6], acc[i][7]);
    }
}

// =======================================================================
// Phase 2: persistent LSTM recurrence.
// Grid = 128 CTAs x 256 threads (all co-resident on 148 SMs).
// CTA (cg, ks): columns [cg*128, cg*128+128), K slice [ks*64, ks*64+64).
// Wr slice (64x128 = 32 KB) lives in SMEM for all 512 steps.
// Per step: phase A (partial GEMM into g_zpart) -> barrier ->
//           phase B (reduce 8 partials + gates + state update) -> barrier.
// Cross-CTA-written globals are read with __ldcg (L1 is stale inside a
// persistent kernel on sm_103a).
// =======================================================================
__global__ __launch_bounds__(256) void lstm_recur(const float* __restrict__ Wr,
                                                  const float* __restrict__ bias,
                                                  float* __restrict__ out) {
    extern __shared__ float smem[];
    float* Wr_s = smem;             // [64][128]
    float* h_s  = smem + 64 * 128;  // [64][68]  (pad 68 -> conflict-free, 16B-aligned rows)

    const int tid = threadIdx.x;
    const int blk = blockIdx.x;
    const int cg = blk >> 3;        // 0..15  column group
    const int ks = blk & 7;         // 0..7   K slice
    const int tcol = tid & 15;      // col group within CTA tile
    const int tb   = tid >> 4;      // batch group (4 batches each)

    // Load persistent Wr slice: rows ks*64..+64, cols cg*128..+128
#pragma unroll
    for (int r = 0; r < 8; r++) {
        int idx = r * 256 + tid;
        int kl = idx >> 5;
        int c4 = (idx & 31) * 4;
        float4 v = __ldg((const float4*)(Wr + (size_t)(ks * 64 + kl) * NG + cg * 128 + c4));
        *(float4*)&Wr_s[kl * 128 + c4] = v;
    }

    // Init state: gid == b*512 + u  (exactly B*U threads in grid)
    const int gid = blk * 256 + tid;
    const int ub = gid & 511;       // unit
    const int bb = gid >> 9;        // batch
    g_h[0][gid] = 0.0f;
    g_c[gid] = 0.0f;
    grid_barrier(128);              // also fences Wr_s/init before use

    for (int t = 0; t < TT; t++) {
        const int cur = t & 1;

        // ---- Phase A: stage h slice, compute partial GEMM ----
#pragma unroll
        for (int r = 0; r < 4; r++) {
            int idx = r * 256 + tid;
            int b = idx >> 4;
            int k4 = (idx & 15) * 4;
            float4 v = __ldcg((const float4*)&g_h[cur][b * UU + ks * 64 + k4]);
            *(float4*)&h_s[b * 68 + k4] = v;
        }
        __syncthreads();

        float acc[4][8];
#pragma unroll
        for (int i = 0; i < 4; i++)
#pragma unroll
            for (int j = 0; j < 8; j++) acc[i][j] = 0.0f;

#pragma unroll 2
        for (int k0 = 0; k0 < 64; k0 += 4) {
            float hr[4][4];
#pragma unroll
            for (int i = 0; i < 4; i++)
                *(float4*)hr[i] = *(const float4*)&h_s[(tb * 4 + i) * 68 + k0];
#pragma unroll
            for (int kk = 0; kk < 4; kk++) {
                float4 w0 = *(const float4*)&Wr_s[(k0 + kk) * 128 + tcol * 4];
                float4 w1 = *(const float4*)&Wr_s[(k0 + kk) * 128 + 64 + tcol * 4];
#pragma unroll
                for (int i = 0; i < 4; i++) {
                    float hv = hr[i][kk];
                    acc[i][0] = fmaf(hv, w0.x, acc[i][0]);
                    acc[i][1] = fmaf(hv, w0.y, acc[i][1]);
                    acc[i][2] = fmaf(hv, w0.z, acc[i][2]);
                    acc[i][3] = fmaf(hv, w0.w, acc[i][3]);
                    acc[i][4] = fmaf(hv, w1.x, acc[i][4]);
                    acc[i][5] = fmaf(hv, w1.y, acc[i][5]);
                    acc[i][6] = fmaf(hv, w1.z, acc[i][6]);
                    acc[i][7] = fmaf(hv, w1.w, acc[i][7]);
                }
            }
        }
#pragma unroll
        for (int i = 0; i < 4; i++) {
            int b = tb * 4 + i;
            float* zp = &g_zpart[((size_t)ks * BB + b) * NG + cg * 128];
            *(float4*)(zp + tcol * 4)      = make_float4(acc[i][0], acc[i][1], acc[i][2], acc[i][3]);
            *(float4*)(zp + 64 + tcol * 4) = make_float4(acc[i][4], acc[i][5], acc[i][6], acc[i][7]);
        }
        grid_barrier(128);

        // ---- Phase B: reduce partials + gates, thread = (bb, ub) ----
        {
            const float* zxp = &g_zx[(size_t)(bb * TT + t) * NG];
            float z0 = bias[ub]            + zxp[ub];
            float z1 = bias[512 + ub]      + zxp[512 + ub];
            float z2 = bias[1024 + ub]     + zxp[1024 + ub];
            float z3 = bias[1536 + ub]     + zxp[1536 + ub];
#pragma unroll
            for (int s = 0; s < 8; s++) {
                const float* zp = &g_zpart[((size_t)s * BB + bb) * NG];
                z0 += __ldcg(zp + ub);
                z1 += __ldcg(zp + 512 + ub);
                z2 += __ldcg(zp + 1024 + ub);
                z3 += __ldcg(zp + 1536 + ub);
            }
            float ig = 1.0f / (1.0f + expf(-z0));
            float fg = 1.0f / (1.0f + expf(-z1));
            float gg = tanhf(z2);
            float og = 1.0f / (1.0f + expf(-z3));
            float cv = fg * __ldcg(&g_c[gid]) + ig * gg;
            float hv = og * tanhf(cv);
            g_c[gid] = cv;
            g_h[cur ^ 1][gid] = hv;
            if (t == TT - 1) out[gid] = hv;
        }
        grid_barrier(128);
    }
}

// =======================================================================
extern "C" void kernel_launch(void* const* d_in, const int* in_sizes, int n_in,
                              void* d_out, int out_size) {
    const float* x  = (const float*)d_in[0];
    const float* Wk = (const float*)d_in[1];
    const float* Wr = (const float*)d_in[2];
    const float* b  = (const float*)d_in[3];
    float* out = (float*)d_out;

    const int smem_bytes = (64 * 128 + 64 * 68) * sizeof(float);  // 50176
    cudaFuncSetAttribute(lstm_recur, cudaFuncAttributeMaxDynamicSharedMemorySize, smem_bytes);

    dim3 g1(NG / 128, (BB * TT) / 128);   // (16, 256)
    sgemm_zx<<<g1, 256>>>(x, Wk);
    lstm_recur<<<128, 256, smem_bytes>>>(Wr, b, out);
}

// round 3
// speedup vs baseline: 1.1796x; 1.1796x over previous
#include <cuda_runtime.h>
#include <cuda_bf16.h>
#include <cstdint>

#define BB 64
#define TT 512
#define DD 512
#define UU 512
#define NG 2048       // 4*UU
#define MM (BB * TT)  // 32768

// ---------------- device scratch (static: no allocations allowed) ----------------
__device__ float g_zx[(size_t)MM * NG];              // 268 MB: x @ Wk
__device__ __nv_bfloat16 g_xhi[(size_t)MM * DD];     // 32 MB
__device__ __nv_bfloat16 g_xlo[(size_t)MM * DD];     // 32 MB
__device__ __nv_bfloat16 g_wthi[(size_t)NG * DD];    // 2 MB (Wk transposed [N][K])
__device__ __nv_bfloat16 g_wtlo[(size_t)NG * DD];    // 2 MB
__device__ float g_zpart[(size_t)8 * BB * NG];       // 4 MB split-K partials
__device__ float g_h[2][BB * UU];
__device__ float g_c[BB * UU];
__device__ unsigned g_bar_count;
__device__ unsigned g_bar_gen;

// ---------------- helpers (arch-agnostic PTX only: works via compute_103) --------
__device__ __forceinline__ uint32_t smem_u32(const void* p) {
    uint32_t a;
    asm("{ .reg .u64 t; cvta.to.shared.u64 t, %1; cvt.u32.u64 %0, t; }" : "=r"(a) : "l"(p));
    return a;
}
#define SWZ128(b) ((b) ^ (((b) >> 3) & 0x70))

__device__ __forceinline__ void cp16(uint32_t saddr, const void* gptr) {
    asm volatile("cp.async.cg.shared.global [%0], [%1], 16;" :: "r"(saddr), "l"(gptr) : "memory");
}
#define CP_COMMIT() asm volatile("cp.async.commit_group;" ::: "memory")
#define CP_WAIT1()  asm volatile("cp.async.wait_group 1;" ::: "memory")

__device__ __forceinline__ void ldsm_x4(uint32_t* r, uint32_t addr) {
    asm volatile("ldmatrix.sync.aligned.m8n8.x4.shared.b16 {%0,%1,%2,%3}, [%4];"
                 : "=r"(r[0]), "=r"(r[1]), "=r"(r[2]), "=r"(r[3]) : "r"(addr));
}
__device__ __forceinline__ void ldsm_x2(uint32_t* r, uint32_t addr) {
    asm volatile("ldmatrix.sync.aligned.m8n8.x2.shared.b16 {%0,%1}, [%2];"
                 : "=r"(r[0]), "=r"(r[1]) : "r"(addr));
}
__device__ __forceinline__ void mma_bf16(float* c, const uint32_t* a, const uint32_t* b) {
    asm volatile(
        "mma.sync.aligned.m16n8k16.row.col.f32.bf16.bf16.f32 "
        "{%0,%1,%2,%3}, {%4,%5,%6,%7}, {%8,%9}, {%0,%1,%2,%3};"
        : "+f"(c[0]), "+f"(c[1]), "+f"(c[2]), "+f"(c[3])
        : "r"(a[0]), "r"(a[1]), "r"(a[2]), "r"(a[3]), "r"(b[0]), "r"(b[1]));
}

// ---------------- grid-wide barrier (all CTAs co-resident) ----------------
__device__ __forceinline__ void grid_barrier(int nblk) {
    __threadfence();
    __syncthreads();
    if (threadIdx.x == 0) {
        unsigned gen = *(volatile unsigned*)&g_bar_gen;
        if (atomicAdd(&g_bar_count, 1) == (unsigned)(nblk - 1)) {
            g_bar_count = 0;
            __threadfence();
            atomicAdd(&g_bar_gen, 1);
        } else {
            while (*(volatile unsigned*)&g_bar_gen == gen) { __nanosleep(64); }
        }
    }
    __syncthreads();
}

// =======================================================================
// Prep 1: x fp32 -> bf16 hi/lo split, same [M, K] row-major layout.
// =======================================================================
__global__ __launch_bounds__(256) void prep_x(const float* __restrict__ x) {
    size_t i = (size_t)blockIdx.x * 256 + threadIdx.x;  // float4 index
    const size_t n4 = (size_t)MM * DD / 4;
    if (i >= n4) return;
    float4 v = ((const float4*)x)[i];
    __nv_bfloat16 h0 = __float2bfloat16(v.x), h1 = __float2bfloat16(v.y);
    __nv_bfloat16 h2 = __float2bfloat16(v.z), h3 = __float2bfloat16(v.w);
    __nv_bfloat16 l0 = __float2bfloat16(v.x - __bfloat162float(h0));
    __nv_bfloat16 l1 = __float2bfloat16(v.y - __bfloat162float(h1));
    __nv_bfloat16 l2 = __float2bfloat16(v.z - __bfloat162float(h2));
    __nv_bfloat16 l3 = __float2bfloat16(v.w - __bfloat162float(h3));
    ((__nv_bfloat162*)g_xhi)[2 * i]     = __nv_bfloat162(h0, h1);
    ((__nv_bfloat162*)g_xhi)[2 * i + 1] = __nv_bfloat162(h2, h3);
    ((__nv_bfloat162*)g_xlo)[2 * i]     = __nv_bfloat162(l0, l1);
    ((__nv_bfloat162*)g_xlo)[2 * i + 1] = __nv_bfloat162(l2, l3);
}

// =======================================================================
// Prep 2: Wk [K=512][N=2048] -> transposed bf16 hi/lo [N][K].
// =======================================================================
__global__ __launch_bounds__(256) void prep_w(const float* __restrict__ Wk) {
    __shared__ float s[32][33];
    const int n0 = blockIdx.x * 32;
    const int k0 = blockIdx.y * 32;
    const int tx = threadIdx.x & 31;
    const int ty = threadIdx.x >> 5;  // 0..7
#pragma unroll
    for (int j = 0; j < 32; j += 8)
        s[ty + j][tx] = Wk[(size_t)(k0 + ty + j) * NG + n0 + tx];
    __syncthreads();
#pragma unroll
    for (int j = 0; j < 32; j += 8) {
        float v = s[tx][ty + j];
        __nv_bfloat16 h = __float2bfloat16(v);
        __nv_bfloat16 l = __float2bfloat16(v - __bfloat162float(h));
        size_t o = (size_t)(n0 + ty + j) * DD + k0 + tx;
        g_wthi[o] = h;
        g_wtlo[o] = l;
    }
}

// =======================================================================
// Phase 1 GEMM (mma.sync bf16 x3): zx[M,N] = x[M,K] @ Wk[K,N]
// CTA 128x128, BK=64, 8 warps (warp grid 2m x 4n, warp tile 64x32).
// SW128-swizzled smem tiles, ldmatrix fragment loads, 2-stage cp.async.
// =======================================================================
#define STAGE_BYTES 65536
#define SA_HI 0
#define SA_LO 16384
#define SB_HI 32768
#define SB_LO 49152
#define GEMM_SMEM (2 * STAGE_BYTES)

__device__ __forceinline__ void load_stage(uint32_t sbase, int m0, int n0, int kc, int tid) {
    const uint32_t ksrc = (uint32_t)kc * 128;
    const char* pxh = (const char*)g_xhi;
    const char* pxl = (const char*)g_xlo;
    const char* pwh = (const char*)g_wthi;
    const char* pwl = (const char*)g_wtlo;
#pragma unroll
    for (int i = 0; i < 4; i++) {
        int idx = i * 256 + tid;  // 0..1023
        int row = idx >> 3;
        uint32_t q = (uint32_t)(idx & 7) * 16;
        uint32_t sw = SWZ128((uint32_t)row * 128 + q);
        size_t asrc = (size_t)(m0 + row) * 1024 + ksrc + q;
        size_t bsrc = (size_t)(n0 + row) * 1024 + ksrc + q;
        cp16(sbase + SA_HI + sw, pxh + asrc);
        cp16(sbase + SA_LO + sw, pxl + asrc);
        cp16(sbase + SB_HI + sw, pwh + bsrc);
        cp16(sbase + SB_LO + sw, pwl + bsrc);
    }
}

__global__ __launch_bounds__(256) void gemm_zx_mma() {
    extern __shared__ __align__(1024) char smem[];
    const uint32_t sb = smem_u32(smem);
    const int tid = threadIdx.x;
    const int wid = tid >> 5, lid = tid & 31;
    const int n0 = blockIdx.x * 128, m0 = blockIdx.y * 128;
    const int wm = wid & 1;   // 2 warps along M (64 rows each)
    const int wn = wid >> 1;  // 4 warps along N (32 cols each)

    float acc[4][4][4];
#pragma unroll
    for (int mf = 0; mf < 4; mf++)
#pragma unroll
        for (int nf = 0; nf < 4; nf++)
#pragma unroll
            for (int e = 0; e < 4; e++) acc[mf][nf][e] = 0.0f;

    load_stage(sb, m0, n0, 0, tid);
    CP_COMMIT();

    for (int kc = 0; kc < 8; kc++) {
        if (kc < 7) load_stage(sb + ((kc + 1) & 1) * STAGE_BYTES, m0, n0, kc + 1, tid);
        CP_COMMIT();
        CP_WAIT1();
        __syncthreads();

        const uint32_t st = sb + (kc & 1) * STAGE_BYTES;
        const int la = lid & 15;
        const uint32_t a_koff = (uint32_t)(lid >> 4) * 16;       // x4: lanes 16-31 -> +16B
        const uint32_t b_koff = (uint32_t)((la >> 3) & 1) * 16;  // x2: lanes 8-15 -> +16B

#pragma unroll
        for (int k16 = 0; k16 < 4; k16++) {
            const uint32_t kb = (uint32_t)k16 * 32;
            uint32_t ah[4][4], al[4][4];
#pragma unroll
            for (int mf = 0; mf < 4; mf++) {
                uint32_t row = (uint32_t)(wm * 64 + mf * 16 + la);
                uint32_t sw = SWZ128(row * 128 + kb + a_koff);
                ldsm_x4(ah[mf], st + SA_HI + sw);
                ldsm_x4(al[mf], st + SA_LO + sw);
            }
            uint32_t bh[4][2], bl[4][2];
#pragma unroll
            for (int nf = 0; nf < 4; nf++) {
                uint32_t nrow = (uint32_t)(wn * 32 + nf * 8 + (la & 7));
                uint32_t sw = SWZ128(nrow * 128 + kb + b_koff);
                ldsm_x2(bh[nf], st + SB_HI + sw);
                ldsm_x2(bl[nf], st + SB_LO + sw);
            }
#pragma unroll
            for (int mf = 0; mf < 4; mf++)
#pragma unroll
                for (int nf = 0; nf < 4; nf++) {
                    mma_bf16(acc[mf][nf], ah[mf], bh[nf]);
                    mma_bf16(acc[mf][nf], ah[mf], bl[nf]);
                    mma_bf16(acc[mf][nf], al[mf], bh[nf]);
                }
        }
        __syncthreads();
    }

    // Epilogue: fragment layout -> float2 stores straight to g_zx.
    const int g = lid >> 2, tig = lid & 3;
#pragma unroll
    for (int mf = 0; mf < 4; mf++) {
        int row = m0 + wm * 64 + mf * 16 + g;
        float* b0 = g_zx + (size_t)row * NG + n0 + wn * 32;
        float* b1 = b0 + (size_t)8 * NG;
#pragma unroll
        for (int nf = 0; nf < 4; nf++) {
            *(float2*)(b0 + nf * 8 + 2 * tig) = make_float2(acc[mf][nf][0], acc[mf][nf][1]);
            *(float2*)(b1 + nf * 8 + 2 * tig) = make_float2(acc[mf][nf][2], acc[mf][nf][3]);
        }
    }
}

// =======================================================================
// Phase 2: persistent LSTM recurrence (unchanged — known good).
// =======================================================================
__global__ __launch_bounds__(256) void lstm_recur(const float* __restrict__ Wr,
                                                  const float* __restrict__ bias,
                                                  float* __restrict__ out) {
    extern __shared__ float fsm[];
    float* Wr_s = fsm;             // [64][128]
    float* h_s  = fsm + 64 * 128;  // [64][68]

    const int tid = threadIdx.x;
    const int blk = blockIdx.x;
    const int cg = blk >> 3;
    const int ks = blk & 7;
    const int tcol = tid & 15;
    const int tb   = tid >> 4;

#pragma unroll
    for (int r = 0; r < 8; r++) {
        int idx = r * 256 + tid;
        int kl = idx >> 5;
        int c4 = (idx & 31) * 4;
        float4 v = __ldg((const float4*)(Wr + (size_t)(ks * 64 + kl) * NG + cg * 128 + c4));
        *(float4*)&Wr_s[kl * 128 + c4] = v;
    }

    const int gid = blk * 256 + tid;
    const int ub = gid & 511;
    const int bb = gid >> 9;
    g_h[0][gid] = 0.0f;
    g_c[gid] = 0.0f;
    grid_barrier(128);

    for (int t = 0; t < TT; t++) {
        const int cur = t & 1;
#pragma unroll
        for (int r = 0; r < 4; r++) {
            int idx = r * 256 + tid;
            int b = idx >> 4;
            int k4 = (idx & 15) * 4;
            float4 v = __ldcg((const float4*)&g_h[cur][b * UU + ks * 64 + k4]);
            *(float4*)&h_s[b * 68 + k4] = v;
        }
        __syncthreads();

        float acc[4][8];
#pragma unroll
        for (int i = 0; i < 4; i++)
#pragma unroll
            for (int j = 0; j < 8; j++) acc[i][j] = 0.0f;

#pragma unroll 2
        for (int k0 = 0; k0 < 64; k0 += 4) {
            float hr[4][4];
#pragma unroll
            for (int i = 0; i < 4; i++)
                *(float4*)hr[i] = *(const float4*)&h_s[(tb * 4 + i) * 68 + k0];
#pragma unroll
            for (int kk = 0; kk < 4; kk++) {
                float4 w0 = *(const float4*)&Wr_s[(k0 + kk) * 128 + tcol * 4];
                float4 w1 = *(const float4*)&Wr_s[(k0 + kk) * 128 + 64 + tcol * 4];
#pragma unroll
                for (int i = 0; i < 4; i++) {
                    float hv = hr[i][kk];
                    acc[i][0] = fmaf(hv, w0.x, acc[i][0]);
                    acc[i][1] = fmaf(hv, w0.y, acc[i][1]);
                    acc[i][2] = fmaf(hv, w0.z, acc[i][2]);
                    acc[i][3] = fmaf(hv, w0.w, acc[i][3]);
                    acc[i][4] = fmaf(hv, w1.x, acc[i][4]);
                    acc[i][5] = fmaf(hv, w1.y, acc[i][5]);
                    acc[i][6] = fmaf(hv, w1.z, acc[i][6]);
                    acc[i][7] = fmaf(hv, w1.w, acc[i][7]);
                }
            }
        }
#pragma unroll
        for (int i = 0; i < 4; i++) {
            int b = tb * 4 + i;
            float* zp = &g_zpart[((size_t)ks * BB + b) * NG + cg * 128];
            *(float4*)(zp + tcol * 4)      = make_float4(acc[i][0], acc[i][1], acc[i][2], acc[i][3]);
            *(float4*)(zp + 64 + tcol * 4) = make_float4(acc[i][4], acc[i][5], acc[i][6], acc[i][7]);
        }
        grid_barrier(128);

        {
            const float* zxp = &g_zx[(size_t)(bb * TT + t) * NG];
            float z0 = bias[ub]        + zxp[ub];
            float z1 = bias[512 + ub]  + zxp[512 + ub];
            float z2 = bias[1024 + ub] + zxp[1024 + ub];
            float z3 = bias[1536 + ub] + zxp[1536 + ub];
#pragma unroll
            for (int s = 0; s < 8; s++) {
                const float* zp = &g_zpart[((size_t)s * BB + bb) * NG];
                z0 += __ldcg(zp + ub);
                z1 += __ldcg(zp + 512 + ub);
                z2 += __ldcg(zp + 1024 + ub);
                z3 += __ldcg(zp + 1536 + ub);
            }
            float ig = 1.0f / (1.0f + expf(-z0));
            float fg = 1.0f / (1.0f + expf(-z1));
            float gg = tanhf(z2);
            float og = 1.0f / (1.0f + expf(-z3));
            float cv = fg * __ldcg(&g_c[gid]) + ig * gg;
            float hv = og * tanhf(cv);
            g_c[gid] = cv;
            g_h[cur ^ 1][gid] = hv;
            if (t == TT - 1) out[gid] = hv;
        }
        grid_barrier(128);
    }
}

// =======================================================================
extern "C" void kernel_launch(void* const* d_in, const int* in_sizes, int n_in,
                              void* d_out, int out_size) {
    const float* x  = (const float*)d_in[0];
    const float* Wk = (const float*)d_in[1];
    const float* Wr = (const float*)d_in[2];
    const float* b  = (const float*)d_in[3];
    float* out = (float*)d_out;

    cudaFuncSetAttribute(gemm_zx_mma, cudaFuncAttributeMaxDynamicSharedMemorySize, GEMM_SMEM);
    const int rec_smem = (64 * 128 + 64 * 68) * sizeof(float);
    cudaFuncSetAttribute(lstm_recur, cudaFuncAttributeMaxDynamicSharedMemorySize, rec_smem);

    prep_x<<<(MM * DD / 4 + 255) / 256, 256>>>(x);
    prep_w<<<dim3(NG / 32, DD / 32), 256>>>(Wk);
    gemm_zx_mma<<<dim3(NG / 128, MM / 128), 256, GEMM_SMEM>>>();
    lstm_recur<<<128, 256, rec_smem>>>(Wr, b, out);
}

// round 5
// speedup vs baseline: 1.6417x; 1.3917x over previous
#include <cuda_runtime.h>
#include <cuda_bf16.h>
#include <cstdint>

#define BB 64
#define TT 512
#define DD 512
#define UU 512
#define NG 2048       // 4*UU
#define MM (BB * TT)  // 32768

// ---------------- device scratch (static: no allocations allowed) ----------------
__device__ float g_zx[(size_t)MM * NG];              // 268 MB: x @ Wk
__device__ __nv_bfloat16 g_xhi[(size_t)MM * DD];     // 32 MB
__device__ __nv_bfloat16 g_xlo[(size_t)MM * DD];     // 32 MB
__device__ __nv_bfloat16 g_wthi[(size_t)NG * DD];    // 2 MB (Wk^T [N][K])
__device__ __nv_bfloat16 g_wtlo[(size_t)NG * DD];    // 2 MB
__device__ __nv_bfloat16 g_wrhi[(size_t)NG * DD];    // 2 MB (Wr^T [N][K])
__device__ __nv_bfloat16 g_wrlo[(size_t)NG * DD];    // 2 MB
__device__ float g_zpart[(size_t)8 * BB * NG];       // 4 MB split-K partials
__device__ __nv_bfloat16 g_hhi[BB * UU];             // hidden state bf16 hi
__device__ __nv_bfloat16 g_hlo[BB * UU];             // hidden state bf16 lo
__device__ unsigned g_ctr;                            // monotonic barrier counter (memset per launch)

// ---------------- helpers (arch-agnostic PTX only: compiles via compute_103) -----
__device__ __forceinline__ uint32_t smem_u32(const void* p) {
    uint32_t a;
    asm("{ .reg .u64 t; cvta.to.shared.u64 t, %1; cvt.u32.u64 %0, t; }" : "=r"(a) : "l"(p));
    return a;
}
#define SWZ128(b) ((b) ^ (((b) >> 3) & 0x70))

__device__ __forceinline__ void cp16(uint32_t saddr, const void* gptr) {
    asm volatile("cp.async.cg.shared.global [%0], [%1], 16;" :: "r"(saddr), "l"(gptr) : "memory");
}
#define CP_COMMIT() asm volatile("cp.async.commit_group;" ::: "memory")
#define CP_WAIT1()  asm volatile("cp.async.wait_group 1;" ::: "memory")

__device__ __forceinline__ void ldsm_x4(uint32_t* r, uint32_t addr) {
    asm volatile("ldmatrix.sync.aligned.m8n8.x4.shared.b16 {%0,%1,%2,%3}, [%4];"
                 : "=r"(r[0]), "=r"(r[1]), "=r"(r[2]), "=r"(r[3]) : "r"(addr));
}
__device__ __forceinline__ void ldsm_x2(uint32_t* r, uint32_t addr) {
    asm volatile("ldmatrix.sync.aligned.m8n8.x2.shared.b16 {%0,%1}, [%2];"
                 : "=r"(r[0]), "=r"(r[1]) : "r"(addr));
}
__device__ __forceinline__ void mma_bf16(float* c, const uint32_t* a, const uint32_t* b) {
    asm volatile(
        "mma.sync.aligned.m16n8k16.row.col.f32.bf16.bf16.f32 "
        "{%0,%1,%2,%3}, {%4,%5,%6,%7}, {%8,%9}, {%0,%1,%2,%3};"
        : "+f"(c[0]), "+f"(c[1]), "+f"(c[2]), "+f"(c[3])
        : "r"(a[0]), "r"(a[1]), "r"(a[2]), "r"(a[3]), "r"(b[0]), "r"(b[1]));
}
__device__ __forceinline__ unsigned ldcg_u32(const unsigned* p) {
    unsigned v;
    asm volatile("ld.global.cg.u32 %0, [%1];" : "=r"(v) : "l"(p) : "memory");
    return v;
}

// ---------------- fast grid barrier: RED arrival, monotonic counter ----------------
__device__ __forceinline__ void fast_barrier(unsigned tgt) {
    __threadfence();            // release: every thread's prior global writes
    __syncthreads();
    if (threadIdx.x == 0) {
        atomicAdd(&g_ctr, 1u);  // compiles to RED (no-return)
        while (ldcg_u32(&g_ctr) < tgt) __nanosleep(32);
    }
    __syncthreads();
}

// =======================================================================
// Prep 1: x fp32 -> bf16 hi/lo split, same [M, K] row-major layout.
// =======================================================================
__global__ __launch_bounds__(256) void prep_x(const float* __restrict__ x) {
    size_t i = (size_t)blockIdx.x * 256 + threadIdx.x;  // float4 index
    const size_t n4 = (size_t)MM * DD / 4;
    if (i >= n4) return;
    float4 v = ((const float4*)x)[i];
    __nv_bfloat16 h0 = __float2bfloat16(v.x), h1 = __float2bfloat16(v.y);
    __nv_bfloat16 h2 = __float2bfloat16(v.z), h3 = __float2bfloat16(v.w);
    __nv_bfloat16 l0 = __float2bfloat16(v.x - __bfloat162float(h0));
    __nv_bfloat16 l1 = __float2bfloat16(v.y - __bfloat162float(h1));
    __nv_bfloat16 l2 = __float2bfloat16(v.z - __bfloat162float(h2));
    __nv_bfloat16 l3 = __float2bfloat16(v.w - __bfloat162float(h3));
    ((__nv_bfloat162*)g_xhi)[2 * i]     = __nv_bfloat162(h0, h1);
    ((__nv_bfloat162*)g_xhi)[2 * i + 1] = __nv_bfloat162(h2, h3);
    ((__nv_bfloat162*)g_xlo)[2 * i]     = __nv_bfloat162(l0, l1);
    ((__nv_bfloat162*)g_xlo)[2 * i + 1] = __nv_bfloat162(l2, l3);
}

// =======================================================================
// Prep 2: W [K=512][N=2048] fp32 -> transposed bf16 hi/lo [N][K].
// dhi/dlo are DEVICE-RESOLVED pointers (cudaGetSymbolAddress on host!).
// =======================================================================
__global__ __launch_bounds__(256) void prep_wt(const float* __restrict__ W,
                                               __nv_bfloat16* __restrict__ dhi,
                                               __nv_bfloat16* __restrict__ dlo) {
    __shared__ float s[32][33];
    const int n0 = blockIdx.x * 32;
    const int k0 = blockIdx.y * 32;
    const int tx = threadIdx.x & 31;
    const int ty = threadIdx.x >> 5;  // 0..7
#pragma unroll
    for (int j = 0; j < 32; j += 8)
        s[ty + j][tx] = W[(size_t)(k0 + ty + j) * NG + n0 + tx];
    __syncthreads();
#pragma unroll
    for (int j = 0; j < 32; j += 8) {
        float v = s[tx][ty + j];
        __nv_bfloat16 h = __float2bfloat16(v);
        __nv_bfloat16 l = __float2bfloat16(v - __bfloat162float(h));
        size_t o = (size_t)(n0 + ty + j) * DD + k0 + tx;
        dhi[o] = h;
        dlo[o] = l;
    }
}

// =======================================================================
// Phase 1 GEMM (mma.sync bf16 x3): zx[M,N] = x[M,K] @ Wk[K,N]
// (validated in R3, rel_err 6e-6)
// =======================================================================
#define STAGE_BYTES 65536
#define SA_HI 0
#define SA_LO 16384
#define SB_HI 32768
#define SB_LO 49152
#define GEMM_SMEM (2 * STAGE_BYTES)

__device__ __forceinline__ void load_stage(uint32_t sbase, int m0, int n0, int kc, int tid) {
    const uint32_t ksrc = (uint32_t)kc * 128;
    const char* pxh = (const char*)g_xhi;
    const char* pxl = (const char*)g_xlo;
    const char* pwh = (const char*)g_wthi;
    const char* pwl = (const char*)g_wtlo;
#pragma unroll
    for (int i = 0; i < 4; i++) {
        int idx = i * 256 + tid;  // 0..1023
        int row = idx >> 3;
        uint32_t q = (uint32_t)(idx & 7) * 16;
        uint32_t sw = SWZ128((uint32_t)row * 128 + q);
        size_t asrc = (size_t)(m0 + row) * 1024 + ksrc + q;
        size_t bsrc = (size_t)(n0 + row) * 1024 + ksrc + q;
        cp16(sbase + SA_HI + sw, pxh + asrc);
        cp16(sbase + SA_LO + sw, pxl + asrc);
        cp16(sbase + SB_HI + sw, pwh + bsrc);
        cp16(sbase + SB_LO + sw, pwl + bsrc);
    }
}

__global__ __launch_bounds__(256) void gemm_zx_mma() {
    extern __shared__ __align__(1024) char smem[];
    const uint32_t sb = smem_u32(smem);
    const int tid = threadIdx.x;
    const int wid = tid >> 5, lid = tid & 31;
    const int n0 = blockIdx.x * 128, m0 = blockIdx.y * 128;
    const int wm = wid & 1;   // 2 warps along M (64 rows each)
    const int wn = wid >> 1;  // 4 warps along N (32 cols each)

    float acc[4][4][4];
#pragma unroll
    for (int mf = 0; mf < 4; mf++)
#pragma unroll
        for (int nf = 0; nf < 4; nf++)
#pragma unroll
            for (int e = 0; e < 4; e++) acc[mf][nf][e] = 0.0f;

    load_stage(sb, m0, n0, 0, tid);
    CP_COMMIT();

    for (int kc = 0; kc < 8; kc++) {
        if (kc < 7) load_stage(sb + ((kc + 1) & 1) * STAGE_BYTES, m0, n0, kc + 1, tid);
        CP_COMMIT();
        CP_WAIT1();
        __syncthreads();

        const uint32_t st = sb + (kc & 1) * STAGE_BYTES;
        const int la = lid & 15;
        const uint32_t a_koff = (uint32_t)(lid >> 4) * 16;
        const uint32_t b_koff = (uint32_t)((la >> 3) & 1) * 16;

#pragma unroll
        for (int k16 = 0; k16 < 4; k16++) {
            const uint32_t kb = (uint32_t)k16 * 32;
            uint32_t ah[4][4], al[4][4];
#pragma unroll
            for (int mf = 0; mf < 4; mf++) {
                uint32_t row = (uint32_t)(wm * 64 + mf * 16 + la);
                uint32_t sw = SWZ128(row * 128 + kb + a_koff);
                ldsm_x4(ah[mf], st + SA_HI + sw);
                ldsm_x4(al[mf], st + SA_LO + sw);
            }
            uint32_t bh[4][2], bl[4][2];
#pragma unroll
            for (int nf = 0; nf < 4; nf++) {
                uint32_t nrow = (uint32_t)(wn * 32 + nf * 8 + (la & 7));
                uint32_t sw = SWZ128(nrow * 128 + kb + b_koff);
                ldsm_x2(bh[nf], st + SB_HI + sw);
                ldsm_x2(bl[nf], st + SB_LO + sw);
            }
#pragma unroll
            for (int mf = 0; mf < 4; mf++)
#pragma unroll
                for (int nf = 0; nf < 4; nf++) {
                    mma_bf16(acc[mf][nf], ah[mf], bh[nf]);
                    mma_bf16(acc[mf][nf], ah[mf], bl[nf]);
                    mma_bf16(acc[mf][nf], al[mf], bh[nf]);
                }
        }
        __syncthreads();
    }

    const int g = lid >> 2, tig = lid & 3;
#pragma unroll
    for (int mf = 0; mf < 4; mf++) {
        int row = m0 + wm * 64 + mf * 16 + g;
        float* b0 = g_zx + (size_t)row * NG + n0 + wn * 32;
        float* b1 = b0 + (size_t)8 * NG;
#pragma unroll
        for (int nf = 0; nf < 4; nf++) {
            *(float2*)(b0 + nf * 8 + 2 * tig) = make_float2(acc[mf][nf][0], acc[mf][nf][1]);
            *(float2*)(b1 + nf * 8 + 2 * tig) = make_float2(acc[mf][nf][2], acc[mf][nf][3]);
        }
    }
}

// =======================================================================
// Phase 2: persistent LSTM recurrence — TENSORIZED (HMMA bf16 x3).
// 128 CTAs x 256 thr. CTA (cg 0..15, ks 0..7): N-cols [cg*128,+128),
// K-slice [ks*64,+64). Wr^T slice in smem; B-fragments resident in
// registers for all 512 steps; c in a per-thread register.
// =======================================================================
#define R_WHI 0
#define R_WLO 16384
#define R_HHI 32768
#define R_HLO 40960
#define REC_SMEM 49152

__global__ __launch_bounds__(256) void lstm_recur(const float* __restrict__ bias,
                                                  float* __restrict__ out) {
    extern __shared__ __align__(1024) char rsm[];
    const uint32_t sb = smem_u32(rsm);
    const int tid = threadIdx.x;
    const int wid = tid >> 5, lid = tid & 31;
    const int blk = blockIdx.x;
    const int cg = blk >> 3;   // 0..15 column group (128 cols)
    const int ks = blk & 7;    // 0..7  K slice (64 rows)
    const int wn = wid;        // 8 warps along N: 16 cols each

    // ---- load persistent Wr^T slice into smem (SW128) ----
#pragma unroll
    for (int r = 0; r < 4; r++) {
        int i = r * 256 + tid;         // 0..1023
        int row = i >> 3;              // 0..127 (N rows)
        uint32_t q = (uint32_t)(i & 7) * 16;
        uint32_t sw = SWZ128((uint32_t)row * 128 + q);
        size_t src = (size_t)(cg * 128 + row) * 1024 + (size_t)ks * 128 + q;
        *(float4*)(rsm + R_WHI + sw) = *(const float4*)((const char*)g_wrhi + src);
        *(float4*)(rsm + R_WLO + sw) = *(const float4*)((const char*)g_wrlo + src);
    }

    // ---- zero initial hidden state (gid = b*512 + u, one per thread) ----
    const int gid = blk * 256 + tid;
    const int ub = gid & 511;
    const int bb = gid >> 9;
    g_hhi[gid] = __float2bfloat16(0.0f);
    g_hlo[gid] = __float2bfloat16(0.0f);
    float c_reg = 0.0f;
    __syncthreads();

    // ---- preload B fragments (Wr) into registers: kept for all 512 steps ----
    const int la = lid & 15;
    const uint32_t a_koff = (uint32_t)(lid >> 4) * 16;
    const uint32_t b_koff = (uint32_t)((la >> 3) & 1) * 16;
    uint32_t bhfr[2][4][2], blfr[2][4][2];   // [nf][k16][2]
#pragma unroll
    for (int nf = 0; nf < 2; nf++)
#pragma unroll
        for (int k16 = 0; k16 < 4; k16++) {
            uint32_t nrow = (uint32_t)(wn * 16 + nf * 8 + (la & 7));
            uint32_t sw = SWZ128(nrow * 128 + (uint32_t)k16 * 32 + b_koff);
            ldsm_x2(bhfr[nf][k16], sb + R_WHI + sw);
            ldsm_x2(blfr[nf][k16], sb + R_WLO + sw);
        }

    unsigned tgt = 0;
    tgt += 128; fast_barrier(tgt);   // h zeros visible everywhere

    const int g = lid >> 2, tig = lid & 3;

    for (int t = 0; t < TT; t++) {
        // ---- Phase A: stage h slice (bf16 hi/lo) into smem ----
#pragma unroll
        for (int r = 0; r < 2; r++) {
            int i = r * 256 + tid;      // 0..511
            int row = i >> 3;           // batch 0..63
            uint32_t q = (uint32_t)(i & 7) * 16;
            uint32_t sw = SWZ128((uint32_t)row * 128 + q);
            size_t src = (size_t)row * 1024 + (size_t)ks * 128 + q;
            *(float4*)(rsm + R_HHI + sw) = __ldcg((const float4*)((const char*)g_hhi + src));
            *(float4*)(rsm + R_HLO + sw) = __ldcg((const float4*)((const char*)g_hlo + src));
        }
        __syncthreads();

        float acc[4][2][4];
#pragma unroll
        for (int mf = 0; mf < 4; mf++)
#pragma unroll
            for (int nf = 0; nf < 2; nf++)
#pragma unroll
                for (int e = 0; e < 4; e++) acc[mf][nf][e] = 0.0f;

#pragma unroll
        for (int k16 = 0; k16 < 4; k16++) {
            const uint32_t kb = (uint32_t)k16 * 32;
            uint32_t ah[4][4], al[4][4];
#pragma unroll
            for (int mf = 0; mf < 4; mf++) {
                uint32_t row = (uint32_t)(mf * 16 + la);
                uint32_t sw = SWZ128(row * 128 + kb + a_koff);
                ldsm_x4(ah[mf], sb + R_HHI + sw);
                ldsm_x4(al[mf], sb + R_HLO + sw);
            }
#pragma unroll
            for (int mf = 0; mf < 4; mf++)
#pragma unroll
                for (int nf = 0; nf < 2; nf++) {
                    mma_bf16(acc[mf][nf], ah[mf], bhfr[nf][k16]);
                    mma_bf16(acc[mf][nf], ah[mf], blfr[nf][k16]);
                    mma_bf16(acc[mf][nf], al[mf], bhfr[nf][k16]);
                }
        }

        // ---- write split-K partials ----
#pragma unroll
        for (int mf = 0; mf < 4; mf++) {
            int b0r = mf * 16 + g;
#pragma unroll
            for (int nf = 0; nf < 2; nf++) {
                int col = cg * 128 + wn * 16 + nf * 8 + 2 * tig;
                float* z0 = &g_zpart[((size_t)ks * BB + b0r) * NG + col];
                float* z1 = &g_zpart[((size_t)ks * BB + b0r + 8) * NG + col];
                *(float2*)z0 = make_float2(acc[mf][nf][0], acc[mf][nf][1]);
                *(float2*)z1 = make_float2(acc[mf][nf][2], acc[mf][nf][3]);
            }
        }
        tgt += 128; fast_barrier(tgt);

        // ---- Phase B: reduce partials + gates (thread = (bb, ub)) ----
        {
            const float* zxp = &g_zx[(size_t)(bb * TT + t) * NG];
            float z0 = bias[ub]        + __ldg(zxp + ub);
            float z1 = bias[512 + ub]  + __ldg(zxp + 512 + ub);
            float z2 = bias[1024 + ub] + __ldg(zxp + 1024 + ub);
            float z3 = bias[1536 + ub] + __ldg(zxp + 1536 + ub);
#pragma unroll
            for (int s = 0; s < 8; s++) {
                const float* zp = &g_zpart[((size_t)s * BB + bb) * NG];
                z0 += __ldcg(zp + ub);
                z1 += __ldcg(zp + 512 + ub);
                z2 += __ldcg(zp + 1024 + ub);
                z3 += __ldcg(zp + 1536 + ub);
            }
            float ig = 1.0f / (1.0f + expf(-z0));
            float fg = 1.0f / (1.0f + expf(-z1));
            float gg = tanhf(z2);
            float og = 1.0f / (1.0f + expf(-z3));
            float cv = fg * c_reg + ig * gg;
            c_reg = cv;
            float hv = og * tanhf(cv);
            __nv_bfloat16 hh = __float2bfloat16(hv);
            g_hhi[gid] = hh;
            g_hlo[gid] = __float2bfloat16(hv - __bfloat162float(hh));
            if (t == TT - 1) out[gid] = hv;
        }
        tgt += 128; fast_barrier(tgt);
    }
}

// =======================================================================
extern "C" void kernel_launch(void* const* d_in, const int* in_sizes, int n_in,
                              void* d_out, int out_size) {
    const float* x  = (const float*)d_in[0];
    const float* Wk = (const float*)d_in[1];
    const float* Wr = (const float*)d_in[2];
    const float* b  = (const float*)d_in[3];
    float* out = (float*)d_out;

    cudaFuncSetAttribute(gemm_zx_mma, cudaFuncAttributeMaxDynamicSharedMemorySize, GEMM_SMEM);
    cudaFuncSetAttribute(lstm_recur, cudaFuncAttributeMaxDynamicSharedMemorySize, REC_SMEM);

    // Resolve DEVICE addresses of __device__ symbols on the host (the R4 bug:
    // passing the symbols directly gives the host-side shadow address).
    void* ctr_ptr = nullptr;
    void *wthi, *wtlo, *wrhi, *wrlo;
    cudaGetSymbolAddress(&ctr_ptr, g_ctr);
    cudaGetSymbolAddress(&wthi, g_wthi);
    cudaGetSymbolAddress(&wtlo, g_wtlo);
    cudaGetSymbolAddress(&wrhi, g_wrhi);
    cudaGetSymbolAddress(&wrlo, g_wrlo);

    cudaMemsetAsync(ctr_ptr, 0, sizeof(unsigned));   // graph-capturable, stream-ordered

    prep_x<<<(MM * DD / 4 + 255) / 256, 256>>>(x);
    prep_wt<<<dim3(NG / 32, DD / 32), 256>>>(Wk, (__nv_bfloat16*)wthi, (__nv_bfloat16*)wtlo);
    prep_wt<<<dim3(NG / 32, DD / 32), 256>>>(Wr, (__nv_bfloat16*)wrhi, (__nv_bfloat16*)wrlo);
    gemm_zx_mma<<<dim3(NG / 128, MM / 128), 256, GEMM_SMEM>>>();
    lstm_recur<<<128, 256, REC_SMEM>>>(b, out);
}